// round 3
// baseline (speedup 1.0000x reference)
#include <cuda_runtime.h>
#include <cuda_bf16.h>
#include <stdint.h>

#define BB 8
#define AA 26880
#define KK 2048
#define CAP 4096        // valid-candidate capacity per batch (Nv ~ 1344)
#define PCAP 2048       // conflict-pair capacity per batch (expected ~10)
#define NCH 105         // 26880/256 chunks per batch
#define NCHALL (BB*NCH) // 840
#define NBLK 128
#define NTHR 256
#define NWRP (NBLK*8)   // 1024 warps
#define TILE 64

// ---------------- device scratch (counters restored to 0 at end of each launch) ----------------
__device__ unsigned            g_cnt[BB];
__device__ unsigned long long  g_valid[BB][CAP];
__device__ int                 g_nv[BB];
__device__ float4              g_boxes[BB][KK];
__device__ unsigned            g_paircnt[BB];
__device__ unsigned            g_pairs[BB][PCAP];
__device__ unsigned            g_invcnt[BB][NCH];
__device__ unsigned            g_barcnt;   // returns to 0 after every barrier
__device__ unsigned            g_bargen;   // monotonic generation counter

// ---------------- software grid barrier (all NBLK blocks co-resident: NBLK <= #SMs) ----------------
__device__ __forceinline__ void gridbar() {
    __syncthreads();
    if (threadIdx.x == 0) {
        volatile unsigned* vgen = &g_bargen;
        unsigned gen = *vgen;                 // read before arriving
        __threadfence();                      // release block's prior stores
        unsigned v = atomicAdd(&g_barcnt, 1u);
        if (v == NBLK - 1) {                  // last arriver
            g_barcnt = 0;
            __threadfence();
            atomicAdd(&g_bargen, 1u);         // release everyone
        } else {
            while (*vgen == gen) __nanosleep(40);
        }
        __threadfence();                      // acquire
    }
    __syncthreads();
}

__global__ void __launch_bounds__(NTHR) k_all(const float* __restrict__ preds,
                                              float* __restrict__ out) {
    __shared__ unsigned      swarp[8];
    __shared__ float4        sbi[TILE];
    __shared__ float         sai[TILE];
    __shared__ float4        sbj[TILE];
    __shared__ float         saj[TILE];
    __shared__ unsigned      sp[PCAP];        // 8 KB (resolve)
    __shared__ unsigned char skeep[KK];       // 2 KB (resolve)

    const int t    = threadIdx.x;
    const int wid  = t >> 5;
    const int lane = t & 31;
    const int W    = blockIdx.x * 8 + wid;    // global warp id [0, NWRP)

    // ======== Phase A: compact valid candidates + per-chunk invalid counts ========
    for (int id = blockIdx.x; id < NCHALL; id += NBLK) {
        int b = id / NCH, cl = id % NCH;
        int a = cl * 256 + t;
        float s = preds[(size_t)b * 5 * AA + (size_t)4 * AA + a];
        bool val = (s >= 0.1f);
        if (val) {
            unsigned pos = atomicAdd(&g_cnt[b], 1u);
            if (pos < CAP) {
                // key: score desc, idx asc on ties (positive floats are bit-order-preserving)
                g_valid[b][pos] =
                    ((unsigned long long)__float_as_uint(s) << 32) |
                    (unsigned long long)(0xFFFFFFFFu - (unsigned)a);
            }
        }
        unsigned bal = __ballot_sync(0xFFFFFFFFu, !val);
        if (lane == 0) swarp[wid] = (unsigned)__popc(bal);
        __syncthreads();
        if (t == 0) {
            unsigned sum = 0;
            #pragma unroll
            for (int q = 0; q < 8; q++) sum += swarp[q];
            g_invcnt[b][cl] = sum;
        }
        __syncthreads();
    }

    gridbar();   // ---- bar 1: counts + keys + invcnt complete ----

    // ======== Phase B1: publish Nv ========
    if (blockIdx.x == 0 && t < BB) {
        unsigned c = g_cnt[t]; if (c > CAP) c = CAP;
        g_nv[t] = ((int)c < KK) ? (int)c : KK;
    }

    // ======== Phase B2: rank sort (warp per candidate) + fused det/box/keep write ========
    for (int b = 0; b < BB; b++) {
        unsigned cnt = g_cnt[b];
        if (cnt > CAP) cnt = CAP;
        const unsigned long long* keys = g_valid[b];
        const float* base = preds + (size_t)b * 5 * AA;
        for (int c = W; c < (int)cnt; c += NWRP) {
            unsigned long long mykey = __ldg(&keys[c]);
            int r = 0;
            for (int m = lane; m < (int)cnt; m += 32)
                r += (__ldg(&keys[m]) > mykey) ? 1 : 0;
            #pragma unroll
            for (int off = 16; off; off >>= 1)
                r += __shfl_xor_sync(0xFFFFFFFFu, r, off);

            if (r < KK) {   // warp-uniform
                int idx = (int)(0xFFFFFFFFu - (unsigned)(mykey & 0xFFFFFFFFu));
                float score = __uint_as_float((unsigned)(mykey >> 32));
                float v = 0.f;
                if (lane < 4) v = __ldg(&base[(size_t)lane * AA + idx]);
                float cx = __shfl_sync(0xFFFFFFFFu, v, 0);
                float cy = __shfl_sync(0xFFFFFFFFu, v, 1);
                float ww = __shfl_sync(0xFFFFFFFFu, v, 2);
                float hh = __shfl_sync(0xFFFFFFFFu, v, 3);
                if (lane == 0) {
                    float hw = ww * 0.5f, hv = hh * 0.5f;
                    float x1 = cx - hw, y1 = cy - hv, x2 = cx + hw, y2 = cy + hv;
                    g_boxes[b][r] = make_float4(x1, y1, x2, y2);
                    float s1 = x1 * 1.5f + 1.0f;
                    float s2 = y1 * 1.0546875f + 1.0f;
                    float s3 = x2 * 1.5f + 1.0f;
                    float s4 = y2 * 1.0546875f + 1.0f;
                    float* d = out + ((size_t)b * KK + r) * 5;
                    d[0] = (s1 + s3) * 0.5f;
                    d[1] = (s2 + s4) * 0.5f;
                    d[2] = s3 - s1;
                    d[3] = s4 - s2;
                    d[4] = score;
                    out[(size_t)BB * KK * 5 + (size_t)b * KK + r] = 1.0f;
                }
            }
        }
    }

    // ======== Phase B3: tail fill (warp per 256-anchor chunk) ========
    if (W < NCHALL) {
        int b = W / NCH, cl = W % NCH;
        unsigned cnt = g_cnt[b]; if (cnt > CAP) cnt = CAP;
        int Nv = ((int)cnt < KK) ? (int)cnt : KK;
        int needed = KK - Nv;
        if (needed > 0) {
            // prefix = invalid anchors in chunks [0, cl) of this batch
            int pf = 0;
            for (int x = lane; x < cl; x += 32) pf += (int)__ldg(&g_invcnt[b][x]);
            #pragma unroll
            for (int off = 16; off; off >>= 1)
                pf += __shfl_xor_sync(0xFFFFFFFFu, pf, off);

            if (pf < needed) {
                const float* base = preds + (size_t)b * 5 * AA;
                const float* sc = base + (size_t)4 * AA;
                int run = pf;
                #pragma unroll
                for (int g = 0; g < 8; g++) {
                    int a = cl * 256 + g * 32 + lane;
                    float s = sc[a];
                    bool inv = (s < 0.1f);
                    unsigned bal = __ballot_sync(0xFFFFFFFFu, inv);
                    int r = run + __popc(bal & ((1u << lane) - 1u));
                    if (inv && r < needed) {
                        int slot = Nv + r;
                        float cx = base[a], cy = base[AA + a];
                        float ww = base[2 * AA + a], hh = base[3 * AA + a];
                        float hw = ww * 0.5f, hv = hh * 0.5f;
                        float x1 = cx - hw, y1 = cy - hv, x2 = cx + hw, y2 = cy + hv;
                        float s1 = x1 * 1.5f + 1.0f;
                        float s2 = y1 * 1.0546875f + 1.0f;
                        float s3 = x2 * 1.5f + 1.0f;
                        float s4 = y2 * 1.0546875f + 1.0f;
                        float* d = out + ((size_t)b * KK + slot) * 5;
                        d[0] = (s1 + s3) * 0.5f;
                        d[1] = (s2 + s4) * 0.5f;
                        d[2] = s3 - s1;
                        d[3] = s4 - s2;
                        d[4] = -1.0f;
                        out[(size_t)BB * KK * 5 + (size_t)b * KK + slot] = 0.0f;
                    }
                    run += __popc(bal);
                    if (run >= needed) break;   // warp-uniform
                }
            }
        }
    }

    gridbar();   // ---- bar 2: boxes ready ----

    // ======== Phase C: sparse conflict pairs over linearized upper-triangle tiles ========
    {
        int nt[BB], Toff[BB + 1];
        Toff[0] = 0;
        #pragma unroll
        for (int b = 0; b < BB; b++) {
            unsigned c = g_cnt[b]; if (c > CAP) c = CAP;
            int Nv = ((int)c < KK) ? (int)c : KK;
            nt[b] = (Nv + TILE - 1) / TILE;
            Toff[b + 1] = Toff[b] + nt[b] * (nt[b] + 1) / 2;
        }
        int Tall = Toff[BB];

        for (int tx = blockIdx.x; tx < Tall; tx += NBLK) {
            int b = 0;
            while (tx >= Toff[b + 1]) b++;
            int local = tx - Toff[b];
            int ntb = nt[b];
            unsigned c = g_cnt[b]; if (c > CAP) c = CAP;
            int Nv = ((int)c < KK) ? (int)c : KK;

            int i = 0, S = 0;
            while (local >= S + (ntb - i)) { S += ntb - i; i++; }
            int j = i + (local - S);
            int i0 = i * TILE, j0 = j * TILE;

            if (t < TILE) {
                float4 bi = (i0 + t < Nv) ? g_boxes[b][i0 + t] : make_float4(0.f, 0.f, 0.f, 0.f);
                sbi[t] = bi; sai[t] = (bi.z - bi.x) * (bi.w - bi.y);
            } else if (t < 2 * TILE) {
                int u = t - TILE;
                float4 bj = (j0 + u < Nv) ? g_boxes[b][j0 + u] : make_float4(0.f, 0.f, 0.f, 0.f);
                sbj[u] = bj; saj[u] = (bj.z - bj.x) * (bj.w - bj.y);
            }
            __syncthreads();

            int jl = t & 63;
            int jj = j0 + jl;
            if (jj < Nv) {
                float4 bj = sbj[jl];
                float aj = saj[jl];
                #pragma unroll
                for (int q = 0; q < 16; q++) {
                    int ii = (t >> 6) + q * 4;
                    int gi = i0 + ii;
                    if (gi >= Nv || gi >= jj) continue;
                    float4 bi = sbi[ii];
                    float lx = fmaxf(bi.x, bj.x), ly = fmaxf(bi.y, bj.y);
                    float rx = fminf(bi.z, bj.z), ry = fminf(bi.w, bj.w);
                    float iw = fmaxf(rx - lx, 0.f), ih = fmaxf(ry - ly, 0.f);
                    float inter = iw * ih;
                    if (inter > 0.7f * (sai[ii] + aj - inter)) {
                        unsigned pos = atomicAdd(&g_paircnt[b], 1u);
                        if (pos < PCAP)
                            g_pairs[b][pos] = ((unsigned)jj << 16) | (unsigned)gi;
                    }
                }
            }
            __syncthreads();
        }
    }

    gridbar();   // ---- bar 3: pairs complete ----

    // ======== Phase D: greedy resolution (blocks 0..7) + counter reset (block 8) ========
    if (blockIdx.x < BB) {
        int b = blockIdx.x;
        int Nv = g_nv[b];
        unsigned n = g_paircnt[b];
        if (n > PCAP) n = PCAP;

        for (int k = t; k < KK; k += NTHR) skeep[k] = (k < Nv) ? 1 : 0;
        for (unsigned p = t; p < n; p += NTHR) sp[p] = g_pairs[b][p];
        __syncthreads();

        if (t == 0) {
            // sort ascending by packed (j<<16 | i): process suppression targets j ascending
            for (unsigned x = 1; x < n; x++) {
                unsigned v = sp[x];
                int y = (int)x - 1;
                while (y >= 0 && sp[y] > v) { sp[y + 1] = sp[y]; y--; }
                sp[y + 1] = v;
            }
            for (unsigned x = 0; x < n; x++) {
                unsigned v = sp[x];
                int j = (int)(v >> 16), i = (int)(v & 0xFFFFu);
                if (skeep[i] && skeep[j]) {
                    skeep[j] = 0;
                    out[(size_t)BB * KK * 5 + (size_t)b * KK + j] = 0.0f;
                }
            }
            g_paircnt[b] = 0u;   // restore for next launch
        }
    } else if (blockIdx.x == BB) {
        if (t < BB) g_cnt[t] = 0u;   // restore for next launch
    }
}

// ---------------- launch ----------------
extern "C" void kernel_launch(void* const* d_in, const int* in_sizes, int n_in,
                              void* d_out, int out_size) {
    const float* preds = (const float*)d_in[0];
    float* out = (float*)d_out;
    (void)in_sizes; (void)n_in; (void)out_size;

    k_all<<<NBLK, NTHR>>>(preds, out);
}

// round 4
// speedup vs baseline: 1.6712x; 1.6712x over previous
#include <cuda_runtime.h>
#include <cuda_bf16.h>
#include <stdint.h>

#define BB 8
#define AA 26880
#define KK 2048
#define CAP 4096        // valid-candidate capacity per batch (Nv ~ 1344)
#define PCAP 2048       // conflict-pair capacity per batch (expected ~10)
#define NCH 105         // 26880/256 chunks per batch
#define NCHALL (BB*NCH) // 840
#define NBLK 128
#define NTHR 1024
#define NWPB 32         // warps per block
#define TILE 64

// ---------------- device scratch (counters restored to 0 at end of each launch) ----------------
__device__ unsigned            g_cnt[BB];
__device__ unsigned long long  g_valid[BB][CAP];
__device__ int                 g_nv[BB];
__device__ float4              g_boxes[BB][KK];
__device__ unsigned            g_paircnt[BB];
__device__ unsigned            g_pairs[BB][PCAP];
__device__ unsigned            g_invcnt[BB][NCH];
__device__ unsigned            g_barcnt;   // returns to 0 after every barrier
__device__ unsigned            g_bargen;   // monotonic generation counter

// ---------------- software grid barrier (all NBLK blocks co-resident: NBLK <= #SMs) ----------------
__device__ __forceinline__ void gridbar() {
    __syncthreads();
    if (threadIdx.x == 0) {
        volatile unsigned* vgen = &g_bargen;
        unsigned gen = *vgen;                 // read before arriving
        __threadfence();                      // release this block's prior stores
        unsigned v = atomicAdd(&g_barcnt, 1u);
        if (v == NBLK - 1) {                  // last arriver
            g_barcnt = 0;
            __threadfence();
            atomicAdd(&g_bargen, 1u);         // release everyone
        } else {
            while (*vgen == gen) __nanosleep(32);
        }
        __threadfence();                      // acquire
    }
    __syncthreads();
}

// shared memory reused across phases (phases separated by gridbar -> __syncthreads)
union ShMem {
    unsigned long long keys[CAP];                                   // 32 KB (phase B rank)
    struct { float4 bi[TILE]; float ai[TILE];
             float4 bj[TILE]; float aj[TILE]; } pr;                 // 2.5 KB (phase C)
    struct { unsigned sp[PCAP]; unsigned char keep[KK]; } res;      // 10 KB (phase D)
};

__global__ void __launch_bounds__(NTHR) k_all(const float* __restrict__ preds,
                                              float* __restrict__ out) {
    __shared__ ShMem sh;

    const int t    = threadIdx.x;
    const int wid  = t >> 5;
    const int lane = t & 31;
    const int W    = blockIdx.x * NWPB + wid;    // global warp id [0, 4096)

    // ======== Phase A: compact valid candidates (warp-aggregated) + per-chunk invalid counts ========
    if (W < NCHALL) {
        int b = W / NCH, cl = W % NCH;
        const float* sc = preds + (size_t)b * 5 * AA + (size_t)4 * AA + cl * 256;
        unsigned invtot = 0;
        #pragma unroll
        for (int g = 0; g < 8; g++) {
            int a = cl * 256 + g * 32 + lane;
            float s = sc[g * 32 + lane];
            bool val = (s >= 0.1f);
            unsigned bal = __ballot_sync(0xFFFFFFFFu, val);
            int nvw = __popc(bal);
            unsigned base = 0;
            if (lane == 0 && nvw) base = atomicAdd(&g_cnt[b], (unsigned)nvw);
            base = __shfl_sync(0xFFFFFFFFu, base, 0);
            if (val) {
                unsigned pos = base + (unsigned)__popc(bal & ((1u << lane) - 1u));
                if (pos < CAP) {
                    // key: score desc, idx asc on ties (positive floats bit-order-preserving)
                    g_valid[b][pos] =
                        ((unsigned long long)__float_as_uint(s) << 32) |
                        (unsigned long long)(0xFFFFFFFFu - (unsigned)a);
                }
            }
            invtot += (unsigned)(32 - nvw);
        }
        if (lane == 0) g_invcnt[b][cl] = invtot;
    }

    gridbar();   // ---- bar 1: counts + keys + invcnt complete ----

    // ======== Phase B1: publish Nv ========
    if (blockIdx.x == 0 && t < BB) {
        unsigned c = g_cnt[t]; if (c > CAP) c = CAP;
        g_nv[t] = ((int)c < KK) ? (int)c : KK;
    }

    // ======== Phase B2: rank sort via shared keys (16 blocks per batch) ========
    {
        const int bg = blockIdx.x >> 4;          // batch for this block group
        const int bl = blockIdx.x & 15;          // block index within group
        unsigned cnt = g_cnt[bg]; if (cnt > CAP) cnt = CAP;
        const unsigned long long* keys = g_valid[bg];
        const float* base = preds + (size_t)bg * 5 * AA;

        for (int e = t; e < (int)cnt; e += NTHR) sh.keys[e] = keys[e];
        __syncthreads();

        // 512 warp-slots per batch: slot = wid*16 + bl
        for (int c = (wid << 4) | bl; c < (int)cnt; c += 512) {
            unsigned long long mykey = sh.keys[c];
            int r = 0;
            for (int m = lane; m < (int)cnt; m += 32)
                r += (sh.keys[m] > mykey) ? 1 : 0;
            #pragma unroll
            for (int off = 16; off; off >>= 1)
                r += __shfl_xor_sync(0xFFFFFFFFu, r, off);

            if (r < KK) {   // warp-uniform
                int idx = (int)(0xFFFFFFFFu - (unsigned)(mykey & 0xFFFFFFFFu));
                float score = __uint_as_float((unsigned)(mykey >> 32));
                float v = 0.f;
                if (lane < 4) v = __ldg(&base[(size_t)lane * AA + idx]);
                float cx = __shfl_sync(0xFFFFFFFFu, v, 0);
                float cy = __shfl_sync(0xFFFFFFFFu, v, 1);
                float ww = __shfl_sync(0xFFFFFFFFu, v, 2);
                float hh = __shfl_sync(0xFFFFFFFFu, v, 3);
                if (lane == 0) {
                    float hw = ww * 0.5f, hv = hh * 0.5f;
                    float x1 = cx - hw, y1 = cy - hv, x2 = cx + hw, y2 = cy + hv;
                    g_boxes[bg][r] = make_float4(x1, y1, x2, y2);
                    float s1 = x1 * 1.5f + 1.0f;
                    float s2 = y1 * 1.0546875f + 1.0f;
                    float s3 = x2 * 1.5f + 1.0f;
                    float s4 = y2 * 1.0546875f + 1.0f;
                    float* d = out + ((size_t)bg * KK + r) * 5;
                    d[0] = (s1 + s3) * 0.5f;
                    d[1] = (s2 + s4) * 0.5f;
                    d[2] = s3 - s1;
                    d[3] = s4 - s2;
                    d[4] = score;
                    out[(size_t)BB * KK * 5 + (size_t)bg * KK + r] = 1.0f;
                }
            }
        }
    }

    // ======== Phase B3: tail fill (warp per 256-anchor chunk; no shared use) ========
    if (W < NCHALL) {
        int b = W / NCH, cl = W % NCH;
        unsigned cnt = g_cnt[b]; if (cnt > CAP) cnt = CAP;
        int Nv = ((int)cnt < KK) ? (int)cnt : KK;
        int needed = KK - Nv;
        if (needed > 0) {
            int pf = 0;
            for (int x = lane; x < cl; x += 32) pf += (int)__ldg(&g_invcnt[b][x]);
            #pragma unroll
            for (int off = 16; off; off >>= 1)
                pf += __shfl_xor_sync(0xFFFFFFFFu, pf, off);

            if (pf < needed) {
                const float* base = preds + (size_t)b * 5 * AA;
                const float* sc = base + (size_t)4 * AA;
                int run = pf;
                #pragma unroll
                for (int g = 0; g < 8; g++) {
                    int a = cl * 256 + g * 32 + lane;
                    float s = sc[a];
                    bool inv = (s < 0.1f);
                    unsigned bal = __ballot_sync(0xFFFFFFFFu, inv);
                    int r = run + __popc(bal & ((1u << lane) - 1u));
                    if (inv && r < needed) {
                        int slot = Nv + r;
                        float cx = base[a], cy = base[AA + a];
                        float ww = base[2 * AA + a], hh = base[3 * AA + a];
                        float hw = ww * 0.5f, hv = hh * 0.5f;
                        float x1 = cx - hw, y1 = cy - hv, x2 = cx + hw, y2 = cy + hv;
                        float s1 = x1 * 1.5f + 1.0f;
                        float s2 = y1 * 1.0546875f + 1.0f;
                        float s3 = x2 * 1.5f + 1.0f;
                        float s4 = y2 * 1.0546875f + 1.0f;
                        float* d = out + ((size_t)b * KK + slot) * 5;
                        d[0] = (s1 + s3) * 0.5f;
                        d[1] = (s2 + s4) * 0.5f;
                        d[2] = s3 - s1;
                        d[3] = s4 - s2;
                        d[4] = -1.0f;
                        out[(size_t)BB * KK * 5 + (size_t)b * KK + slot] = 0.0f;
                    }
                    run += __popc(bal);
                    if (run >= needed) break;   // warp-uniform
                }
            }
        }
    }

    gridbar();   // ---- bar 2: boxes ready ----

    // ======== Phase C: sparse conflict pairs over linearized upper-triangle tiles ========
    {
        int nt[BB], Toff[BB + 1];
        Toff[0] = 0;
        #pragma unroll
        for (int b = 0; b < BB; b++) {
            unsigned c = g_cnt[b]; if (c > CAP) c = CAP;
            int Nv = ((int)c < KK) ? (int)c : KK;
            nt[b] = (Nv + TILE - 1) / TILE;
            Toff[b + 1] = Toff[b] + nt[b] * (nt[b] + 1) / 2;
        }
        int Tall = Toff[BB];

        for (int tx = blockIdx.x; tx < Tall; tx += NBLK) {
            int b = 0;
            while (tx >= Toff[b + 1]) b++;
            int local = tx - Toff[b];
            int ntb = nt[b];
            unsigned c = g_cnt[b]; if (c > CAP) c = CAP;
            int Nv = ((int)c < KK) ? (int)c : KK;

            int i = 0, S = 0;
            while (local >= S + (ntb - i)) { S += ntb - i; i++; }
            int j = i + (local - S);
            int i0 = i * TILE, j0 = j * TILE;

            if (t < TILE) {
                float4 bi = (i0 + t < Nv) ? g_boxes[b][i0 + t] : make_float4(0.f, 0.f, 0.f, 0.f);
                sh.pr.bi[t] = bi; sh.pr.ai[t] = (bi.z - bi.x) * (bi.w - bi.y);
            } else if (t < 2 * TILE) {
                int u = t - TILE;
                float4 bj = (j0 + u < Nv) ? g_boxes[b][j0 + u] : make_float4(0.f, 0.f, 0.f, 0.f);
                sh.pr.bj[u] = bj; sh.pr.aj[u] = (bj.z - bj.x) * (bj.w - bj.y);
            }
            __syncthreads();

            int jl = t & 63;
            int jj = j0 + jl;
            if (jj < Nv) {
                float4 bj = sh.pr.bj[jl];
                float aj = sh.pr.aj[jl];
                #pragma unroll
                for (int q = 0; q < 4; q++) {
                    int ii = (t >> 6) + q * 16;
                    int gi = i0 + ii;
                    if (gi >= Nv || gi >= jj) continue;
                    float4 bi = sh.pr.bi[ii];
                    float lx = fmaxf(bi.x, bj.x), ly = fmaxf(bi.y, bj.y);
                    float rx = fminf(bi.z, bj.z), ry = fminf(bi.w, bj.w);
                    float iw = fmaxf(rx - lx, 0.f), ih = fmaxf(ry - ly, 0.f);
                    float inter = iw * ih;
                    // iou > 0.7  <=>  inter > 0.7 * union   (union > 0)
                    if (inter > 0.7f * (sh.pr.ai[ii] + aj - inter)) {
                        unsigned pos = atomicAdd(&g_paircnt[b], 1u);
                        if (pos < PCAP)
                            g_pairs[b][pos] = ((unsigned)jj << 16) | (unsigned)gi;
                    }
                }
            }
            __syncthreads();
        }
    }

    gridbar();   // ---- bar 3: pairs complete ----

    // ======== Phase D: greedy resolution (blocks 0..7) + counter reset (block 8) ========
    if (blockIdx.x < BB) {
        int b = blockIdx.x;
        int Nv = g_nv[b];
        unsigned n = g_paircnt[b];
        if (n > PCAP) n = PCAP;

        for (int k = t; k < KK; k += NTHR) sh.res.keep[k] = (k < Nv) ? 1 : 0;
        for (unsigned p = t; p < n; p += NTHR) sh.res.sp[p] = g_pairs[b][p];
        __syncthreads();

        if (t == 0) {
            // sort ascending by packed (j<<16 | i): process suppression targets j ascending
            for (unsigned x = 1; x < n; x++) {
                unsigned v = sh.res.sp[x];
                int y = (int)x - 1;
                while (y >= 0 && sh.res.sp[y] > v) { sh.res.sp[y + 1] = sh.res.sp[y]; y--; }
                sh.res.sp[y + 1] = v;
            }
            for (unsigned x = 0; x < n; x++) {
                unsigned v = sh.res.sp[x];
                int j = (int)(v >> 16), i = (int)(v & 0xFFFFu);
                if (sh.res.keep[i] && sh.res.keep[j]) {
                    sh.res.keep[j] = 0;
                    out[(size_t)BB * KK * 5 + (size_t)b * KK + j] = 0.0f;
                }
            }
            g_paircnt[b] = 0u;   // restore for next launch
        }
    } else if (blockIdx.x == BB) {
        if (t < BB) g_cnt[t] = 0u;   // restore for next launch
    }
}

// ---------------- launch ----------------
extern "C" void kernel_launch(void* const* d_in, const int* in_sizes, int n_in,
                              void* d_out, int out_size) {
    const float* preds = (const float*)d_in[0];
    float* out = (float*)d_out;
    (void)in_sizes; (void)n_in; (void)out_size;

    k_all<<<NBLK, NTHR>>>(preds, out);
}

// round 5
// speedup vs baseline: 1.9098x; 1.1428x over previous
#include <cuda_runtime.h>
#include <cuda_bf16.h>
#include <stdint.h>

#define BB 8
#define AA 26880
#define KK 2048
#define NCH 105          // 26880/256 chunks per batch
#define SCAP 4096        // staged-key capacity (Nv ~ 1344)
#define PCAP 2048        // conflict-pair capacity per batch (expected ~10)
#define TILE 64

// ---------------- device scratch ----------------
// No counter here requires zero-initialization across launches except
// g_paircnt/g_tiledone, whose zero state is restored by the K3 winner block.
__device__ unsigned            g_cvcnt[BB * NCH];          // per-chunk valid count (overwritten each launch)
__device__ unsigned long long  g_ckeys[BB * NCH * 256];    // chunk-local compacted keys
__device__ int                 g_nv[BB];
__device__ float4              g_boxes[BB][KK];
__device__ unsigned            g_paircnt[BB];              // 0 at entry, reset by winner
__device__ unsigned            g_pairs[BB][PCAP];
__device__ unsigned            g_tiledone[BB];             // 0 at entry, reset by winner

// ======== K1: deterministic chunked compaction (no atomics) ========
// key = (score_bits << 32) | (0xFFFFFFFF - idx): descending key order gives
// score desc, idx asc on ties (positive floats are bit-order-preserving).
__global__ void __launch_bounds__(256) k1_compact(const float* __restrict__ preds) {
    int b = blockIdx.y, cl = blockIdx.x;
    int t = threadIdx.x, wid = t >> 5, lane = t & 31;
    __shared__ unsigned wcnt[8];

    int a = cl * 256 + t;
    float s = preds[(size_t)b * 5 * AA + (size_t)4 * AA + a];
    bool val = (s >= 0.1f);
    unsigned bal = __ballot_sync(0xFFFFFFFFu, val);
    if (lane == 0) wcnt[wid] = (unsigned)__popc(bal);
    __syncthreads();
    unsigned wbase = 0;
    #pragma unroll
    for (int q = 0; q < 8; q++) if (q < wid) wbase += wcnt[q];
    if (val) {
        unsigned pos = wbase + (unsigned)__popc(bal & ((1u << lane) - 1u));
        g_ckeys[((size_t)b * NCH + cl) * 256 + pos] =
            ((unsigned long long)__float_as_uint(s) << 32) |
            (unsigned long long)(0xFFFFFFFFu - (unsigned)a);
    }
    if (t == 0) {
        unsigned tot = 0;
        #pragma unroll
        for (int q = 0; q < 8; q++) tot += wcnt[q];
        g_cvcnt[b * NCH + cl] = tot;
    }
}

// ======== K2: rank sort (blocks 0..31) || tail fill (blocks 32..136) ========
__global__ void __launch_bounds__(256) k2_rank_tail(const float* __restrict__ preds,
                                                    float* __restrict__ out) {
    int b = blockIdx.y, bx = blockIdx.x;
    int t = threadIdx.x, wid = t >> 5, lane = t & 31;

    __shared__ unsigned scv[NCH];
    __shared__ unsigned spref[NCH];
    __shared__ unsigned stot;
    __shared__ unsigned wsum[8];
    __shared__ unsigned long long sk[SCAP];     // 32 KB (rank role only)

    // chunk counts -> shared (both roles need them)
    if (t < NCH) scv[t] = g_cvcnt[b * NCH + t];
    __syncthreads();

    if (bx < 32) {
        // ---- rank role ----
        // exclusive prefix of valid counts (broadcast loop, all lanes read same word)
        {
            unsigned tot = 0, pre = 0;
            #pragma unroll 5
            for (int x = 0; x < NCH; x++) {
                unsigned v = scv[x];
                pre += (x < t) ? v : 0;
                tot += v;
            }
            if (t < NCH) spref[t] = pre;
            if (t == 0) stot = tot;
        }
        __syncthreads();

        unsigned cnt = stot; if (cnt > SCAP) cnt = SCAP;
        int Nv = ((int)cnt < KK) ? (int)cnt : KK;
        if (bx == 0 && t == 0) g_nv[b] = Nv;

        // stage contiguous keys into shared (warp per chunk, strided)
        for (int cl = wid; cl < NCH; cl += 8) {
            unsigned base = spref[cl], n = scv[cl];
            const unsigned long long* src = &g_ckeys[((size_t)b * NCH + cl) * 256];
            for (unsigned j = lane; j < n; j += 32) {
                unsigned dst = base + j;
                if (dst < SCAP) sk[dst] = src[j];
            }
        }
        __syncthreads();

        // warp-per-candidate rank scan over shared keys
        const float* basep = preds + (size_t)b * 5 * AA;
        for (int c = bx * 8 + wid; c < (int)cnt; c += 256) {
            unsigned long long mykey = sk[c];
            int r = 0;
            #pragma unroll 4
            for (int m = lane; m < (int)cnt; m += 32)
                r += (sk[m] > mykey) ? 1 : 0;
            #pragma unroll
            for (int off = 16; off; off >>= 1)
                r += __shfl_xor_sync(0xFFFFFFFFu, r, off);

            if (r < KK) {   // warp-uniform
                int idx = (int)(0xFFFFFFFFu - (unsigned)(mykey & 0xFFFFFFFFu));
                float score = __uint_as_float((unsigned)(mykey >> 32));
                float v = 0.f;
                if (lane < 4) v = __ldg(&basep[(size_t)lane * AA + idx]);
                float cx = __shfl_sync(0xFFFFFFFFu, v, 0);
                float cy = __shfl_sync(0xFFFFFFFFu, v, 1);
                float ww = __shfl_sync(0xFFFFFFFFu, v, 2);
                float hh = __shfl_sync(0xFFFFFFFFu, v, 3);
                if (lane == 0) {
                    float hw = ww * 0.5f, hv = hh * 0.5f;
                    float x1 = cx - hw, y1 = cy - hv, x2 = cx + hw, y2 = cy + hv;
                    g_boxes[b][r] = make_float4(x1, y1, x2, y2);
                    // scale = DET_SCALE/IMG_SIZE = [1.5, 1.0546875] (exact fp32)
                    float s1 = x1 * 1.5f + 1.0f;
                    float s2 = y1 * 1.0546875f + 1.0f;
                    float s3 = x2 * 1.5f + 1.0f;
                    float s4 = y2 * 1.0546875f + 1.0f;
                    float* d = out + ((size_t)b * KK + r) * 5;
                    d[0] = (s1 + s3) * 0.5f;
                    d[1] = (s2 + s4) * 0.5f;
                    d[2] = s3 - s1;
                    d[3] = s4 - s2;
                    d[4] = score;
                    out[(size_t)BB * KK * 5 + (size_t)b * KK + r] = 1.0f;
                }
            }
        }
    } else {
        // ---- tail role: chunk cl = bx - 32, thread t <-> anchor ----
        int cl = bx - 32;
        unsigned tot = 0, vpre = 0;
        #pragma unroll 5
        for (int x = 0; x < NCH; x++) {
            unsigned v = scv[x];
            tot += v;
            vpre += (x < cl) ? v : 0;
        }
        unsigned cnt = tot; if (cnt > SCAP) cnt = SCAP;
        int Nv = ((int)cnt < KK) ? (int)cnt : KK;
        int needed = KK - Nv;
        if (needed <= 0) return;
        int invpre = 256 * cl - (int)vpre;     // invalid anchors before this chunk
        if (invpre >= needed) return;

        int a = cl * 256 + t;
        const float* basep = preds + (size_t)b * 5 * AA;
        float s = basep[(size_t)4 * AA + a];
        bool inv = (s < 0.1f);
        unsigned bal = __ballot_sync(0xFFFFFFFFu, inv);
        if (lane == 0) wsum[wid] = (unsigned)__popc(bal);
        __syncthreads();
        int wbase = 0;
        #pragma unroll
        for (int q = 0; q < 8; q++) if (q < wid) wbase += (int)wsum[q];
        int r = invpre + wbase + __popc(bal & ((1u << lane) - 1u));

        if (inv && r < needed) {
            int slot = Nv + r;
            float cx = basep[a], cy = basep[AA + a];
            float ww = basep[2 * AA + a], hh = basep[3 * AA + a];
            float hw = ww * 0.5f, hv = hh * 0.5f;
            float x1 = cx - hw, y1 = cy - hv, x2 = cx + hw, y2 = cy + hv;
            float s1 = x1 * 1.5f + 1.0f;
            float s2 = y1 * 1.0546875f + 1.0f;
            float s3 = x2 * 1.5f + 1.0f;
            float s4 = y2 * 1.0546875f + 1.0f;
            float* d = out + ((size_t)b * KK + slot) * 5;
            d[0] = (s1 + s3) * 0.5f;
            d[1] = (s2 + s4) * 0.5f;
            d[2] = s3 - s1;
            d[3] = s4 - s2;
            d[4] = -1.0f;
            out[(size_t)BB * KK * 5 + (size_t)b * KK + slot] = 0.0f;
        }
    }
}

// ======== K3: conflict pairs + last-tile-done greedy resolution ========
__global__ void __launch_bounds__(256) k3_pairs_resolve(float* __restrict__ out) {
    int b = blockIdx.y, bx = blockIdx.x;
    int t = threadIdx.x;

    int Nv = __ldg(&g_nv[b]);
    int nt = (Nv + TILE - 1) / TILE;
    int T = nt * (nt + 1) / 2;
    if (bx >= T) return;

    __shared__ float4 sbi[TILE];
    __shared__ float  sai[TILE];
    __shared__ float4 sbj[TILE];
    __shared__ float  saj[TILE];
    __shared__ int    swin;
    __shared__ unsigned sp[PCAP];        // 8 KB (resolve)
    __shared__ unsigned char skeep[KK];  // 2 KB (resolve)

    // linear bx -> upper-triangle tile (i <= j)
    int i = 0, S = 0;
    while (bx >= S + (nt - i)) { S += nt - i; i++; }
    int j = i + (bx - S);
    int i0 = i * TILE, j0 = j * TILE;

    if (t < TILE) {
        float4 bi = (i0 + t < Nv) ? g_boxes[b][i0 + t] : make_float4(0.f, 0.f, 0.f, 0.f);
        sbi[t] = bi; sai[t] = (bi.z - bi.x) * (bi.w - bi.y);
    } else if (t < 2 * TILE) {
        int u = t - TILE;
        float4 bj = (j0 + u < Nv) ? g_boxes[b][j0 + u] : make_float4(0.f, 0.f, 0.f, 0.f);
        sbj[u] = bj; saj[u] = (bj.z - bj.x) * (bj.w - bj.y);
    }
    __syncthreads();

    int jl = t & 63;
    int jj = j0 + jl;
    if (jj < Nv) {
        float4 bj = sbj[jl];
        float aj = saj[jl];
        #pragma unroll
        for (int q = 0; q < 16; q++) {
            int ii = (t >> 6) + q * 4;
            int gi = i0 + ii;
            if (gi >= Nv || gi >= jj) continue;
            float4 bi = sbi[ii];
            float lx = fmaxf(bi.x, bj.x), ly = fmaxf(bi.y, bj.y);
            float rx = fminf(bi.z, bj.z), ry = fminf(bi.w, bj.w);
            float iw = fmaxf(rx - lx, 0.f), ih = fmaxf(ry - ly, 0.f);
            float inter = iw * ih;
            // iou > 0.7  <=>  inter > 0.7 * union   (union > 0)
            if (inter > 0.7f * (sai[ii] + aj - inter)) {
                unsigned pos = atomicAdd(&g_paircnt[b], 1u);
                if (pos < PCAP)
                    g_pairs[b][pos] = ((unsigned)jj << 16) | (unsigned)gi;
            }
        }
    }
    __syncthreads();

    // last-tile-done election
    if (t == 0) {
        __threadfence();                                  // publish this tile's pair writes
        unsigned old = atomicAdd(&g_tiledone[b], 1u);
        swin = (old == (unsigned)(T - 1)) ? 1 : 0;
    }
    __syncthreads();
    if (!swin) return;

    // ---- winner block: exact greedy resolution ----
    __threadfence();    // order: observed final count -> read pairs
    unsigned n = g_paircnt[b];
    if (n > PCAP) n = PCAP;

    for (int k = t; k < KK; k += 256) skeep[k] = (k < Nv) ? 1 : 0;
    for (unsigned p = t; p < n; p += 256) sp[p] = g_pairs[b][p];
    __syncthreads();

    if (t == 0) {
        // sort ascending by packed (j<<16 | i): process suppression targets j ascending
        for (unsigned x = 1; x < n; x++) {
            unsigned v = sp[x];
            int y = (int)x - 1;
            while (y >= 0 && sp[y] > v) { sp[y + 1] = sp[y]; y--; }
            sp[y + 1] = v;
        }
        for (unsigned x = 0; x < n; x++) {
            unsigned v = sp[x];
            int jd = (int)(v >> 16), is = (int)(v & 0xFFFFu);
            if (skeep[is] && skeep[jd]) {
                skeep[jd] = 0;
                out[(size_t)BB * KK * 5 + (size_t)b * KK + jd] = 0.0f;
            }
        }
        g_paircnt[b]  = 0u;   // restore zero-state for next launch
        g_tiledone[b] = 0u;
    }
}

// ---------------- launch ----------------
extern "C" void kernel_launch(void* const* d_in, const int* in_sizes, int n_in,
                              void* d_out, int out_size) {
    const float* preds = (const float*)d_in[0];
    float* out = (float*)d_out;
    (void)in_sizes; (void)n_in; (void)out_size;

    k1_compact      <<<dim3(NCH, BB), 256>>>(preds);
    k2_rank_tail    <<<dim3(NCH + 32, BB), 256>>>(preds, out);
    k3_pairs_resolve<<<dim3(528, BB), 256>>>(out);   // 528 = max tiles (Nv<=2048)
}

// round 7
// speedup vs baseline: 2.5634x; 1.3422x over previous
#include <cuda_runtime.h>
#include <cuda_bf16.h>
#include <stdint.h>

#define BB 8
#define AA 26880
#define KK 2048
#define NCH 105          // 26880/256 chunks per batch
#define SCAP 4096        // staged-key capacity (Nv ~ 1344)
#define PCAP 512         // conflict-pair capacity per batch (expected ~10)
#define RB 32            // rank/tail blocks per batch in K2
#define TILE 64

// ---------------- device scratch ----------------
__device__ unsigned            g_cvcnt[BB * NCH];          // per-chunk valid count
__device__ unsigned long long  g_ckeys[BB * NCH * 256];    // chunk-local compacted keys
__device__ int                 g_nv[BB];
__device__ float4              g_boxes[BB][KK];
__device__ unsigned            g_paircnt[BB];              // 0 at entry, reset by K3 winner
__device__ unsigned            g_pairs[BB][PCAP];
__device__ unsigned            g_tiledone[BB];             // 0 at entry, reset by K3 winner

// ======== K1: vectorized chunked compaction (float4, warp-scan, no atomics) ========
// key = (score_bits << 32) | (0xFFFFFFFF - idx): descending key order gives
// score desc, idx asc on ties (positive floats are bit-order-preserving).
__global__ void __launch_bounds__(256) k1_compact(const float* __restrict__ preds) {
    int b = blockIdx.y;
    int t = threadIdx.x, wid = t >> 5, lane = t & 31;
    __shared__ unsigned swc[8];    // per-warp valid totals

    int a0 = blockIdx.x * 1024 + t * 4;          // 4 consecutive anchors per thread
    bool inb = (a0 < AA);                        // AA % 4 == 0, float4-aligned
    float4 s4 = make_float4(0.f, 0.f, 0.f, 0.f);
    if (inb) s4 = *(const float4*)(preds + (size_t)b * 5 * AA + (size_t)4 * AA + a0);

    unsigned m = 0;
    if (inb) {
        m = (unsigned)(s4.x >= 0.1f)
          | ((unsigned)(s4.y >= 0.1f) << 1)
          | ((unsigned)(s4.z >= 0.1f) << 2)
          | ((unsigned)(s4.w >= 0.1f) << 3);
    }
    int v = __popc(m);
    // warp inclusive scan of v
    int inc = v;
    #pragma unroll
    for (int off = 1; off < 32; off <<= 1) {
        int n = __shfl_up_sync(0xFFFFFFFFu, inc, off);
        if (lane >= off) inc += n;
    }
    int exc = inc - v;
    if (lane == 31) swc[wid] = (unsigned)inc;
    __syncthreads();

    int cib = wid >> 1;                    // chunk within block (0..3), chunk = 2 warps
    int cl = blockIdx.x * 4 + cib;
    if (cl < NCH && inb) {
        unsigned p = (unsigned)exc + ((wid & 1) ? swc[wid - 1] : 0u);
        unsigned long long* dst = &g_ckeys[((size_t)b * NCH + cl) * 256];
        float ss[4] = {s4.x, s4.y, s4.z, s4.w};
        #pragma unroll
        for (int q = 0; q < 4; q++) {
            if ((m >> q) & 1u) {
                dst[p++] =
                    ((unsigned long long)__float_as_uint(ss[q]) << 32) |
                    (unsigned long long)(0xFFFFFFFFu - (unsigned)(a0 + q));
            }
        }
    }
    if (cl < NCH && (t & 63) == 0)
        g_cvcnt[b * NCH + cl] = swc[cib * 2] + swc[cib * 2 + 1];
}

// ======== K2: rank sort (thread-per-candidate, 4-way split scan) + tail fill ========
__global__ void __launch_bounds__(256) k2_rank_tail(const float* __restrict__ preds,
                                                    float* __restrict__ out) {
    int b = blockIdx.y, bl = blockIdx.x;       // bl in [0, RB)
    int t = threadIdx.x, wid = t >> 5, lane = t & 31;

    __shared__ unsigned long long sk[SCAP];    // 32 KB
    __shared__ unsigned scv[NCH];
    __shared__ unsigned scpre[NCH + 1];
    __shared__ unsigned short rp[64][4];
    __shared__ unsigned wsum[8];
    __shared__ unsigned s_cnt;

    if (t < NCH) scv[t] = g_cvcnt[b * NCH + t];
    __syncthreads();
    if (t == 0) {
        unsigned run = 0;
        for (int x = 0; x < NCH; x++) { scpre[x] = run; run += scv[x]; }
        scpre[NCH] = run;
        s_cnt = (run > SCAP) ? SCAP : run;
    }
    __syncthreads();
    unsigned cnt = s_cnt;
    int Nv = ((int)cnt < KK) ? (int)cnt : KK;
    if (bl == 0 && t == 0) g_nv[b] = Nv;

    // stage keys contiguously (warp per chunk)
    for (int cl = wid; cl < NCH; cl += 8) {
        unsigned base = scpre[cl], n = scv[cl];
        const unsigned long long* src = &g_ckeys[((size_t)b * NCH + cl) * 256];
        for (unsigned j = lane; j < n; j += 32) {
            unsigned d = base + j;
            if (d < SCAP) sk[d] = __ldg(&src[j]);
        }
    }
    __syncthreads();

    // ---- rank scan: slot = candidate lane, seg = key segment ----
    int slot = t & 63, seg = t >> 6;           // seg is warp-uniform
    int npass = ((int)cnt + RB * 64 - 1) / (RB * 64);
    const float* basep = preds + (size_t)b * 5 * AA;

    for (int p = 0; p < npass; p++) {
        int c = p * (RB * 64) + bl * 64 + slot;
        bool act = (c < (int)cnt);
        unsigned long long mykey = act ? sk[c] : 0ULL;
        int s0 = (int)(((long long)cnt * seg) >> 2);
        int s1 = (int)(((long long)cnt * (seg + 1)) >> 2);
        int rpart = 0;
        if (act) {
            int mm = s0;
            for (; mm + 4 <= s1; mm += 4) {    // broadcast LDS: all lanes same address
                rpart += (sk[mm]     > mykey);
                rpart += (sk[mm + 1] > mykey);
                rpart += (sk[mm + 2] > mykey);
                rpart += (sk[mm + 3] > mykey);
            }
            for (; mm < s1; mm++) rpart += (sk[mm] > mykey);
        }
        rp[slot][seg] = (unsigned short)rpart;
        __syncthreads();
        if (seg == 0 && act) {
            int r = (int)rp[slot][0] + rp[slot][1] + rp[slot][2] + rp[slot][3];
            if (r < KK) {
                int idx = (int)(0xFFFFFFFFu - (unsigned)(mykey & 0xFFFFFFFFu));
                float score = __uint_as_float((unsigned)(mykey >> 32));
                float cx = __ldg(&basep[idx]);
                float cy = __ldg(&basep[AA + idx]);
                float ww = __ldg(&basep[2 * AA + idx]);
                float hh = __ldg(&basep[3 * AA + idx]);
                float hw = ww * 0.5f, hv = hh * 0.5f;
                float x1 = cx - hw, y1 = cy - hv, x2 = cx + hw, y2 = cy + hv;
                g_boxes[b][r] = make_float4(x1, y1, x2, y2);
                // scale = DET_SCALE/IMG_SIZE = [1.5, 1.0546875] (exact fp32)
                float s1f = x1 * 1.5f + 1.0f;
                float s2f = y1 * 1.0546875f + 1.0f;
                float s3f = x2 * 1.5f + 1.0f;
                float s4f = y2 * 1.0546875f + 1.0f;
                float* d = out + ((size_t)b * KK + r) * 5;
                d[0] = (s1f + s3f) * 0.5f;
                d[1] = (s2f + s4f) * 0.5f;
                d[2] = s3f - s1f;
                d[3] = s4f - s2f;
                d[4] = score;
                out[(size_t)BB * KK * 5 + (size_t)b * KK + r] = 1.0f;
            }
        }
        __syncthreads();
    }

    // ---- tail fill: this block handles chunks bl, bl+RB, ... ----
    int needed = KK - Nv;
    if (needed > 0) {
        const float* sc = basep + (size_t)4 * AA;
        for (int cl = bl; cl < NCH; cl += RB) {
            int invpre = 256 * cl - (int)scpre[cl];   // block-uniform
            if (invpre < needed) {                    // uniform branch
                int a = cl * 256 + t;
                float s = __ldg(&sc[a]);
                bool inv = (s < 0.1f);
                unsigned bal = __ballot_sync(0xFFFFFFFFu, inv);
                if (lane == 0) wsum[wid] = (unsigned)__popc(bal);
                __syncthreads();
                int wbase = 0;
                #pragma unroll
                for (int q = 0; q < 8; q++) if (q < wid) wbase += (int)wsum[q];
                int r = invpre + wbase + __popc(bal & ((1u << lane) - 1u));
                if (inv && r < needed) {
                    int slotk = Nv + r;
                    float cx = basep[a], cy = basep[AA + a];
                    float ww = basep[2 * AA + a], hh = basep[3 * AA + a];
                    float hw = ww * 0.5f, hv = hh * 0.5f;
                    float x1 = cx - hw, y1 = cy - hv, x2 = cx + hw, y2 = cy + hv;
                    float s1f = x1 * 1.5f + 1.0f;
                    float s2f = y1 * 1.0546875f + 1.0f;
                    float s3f = x2 * 1.5f + 1.0f;
                    float s4f = y2 * 1.0546875f + 1.0f;
                    float* d = out + ((size_t)b * KK + slotk) * 5;
                    d[0] = (s1f + s3f) * 0.5f;
                    d[1] = (s2f + s4f) * 0.5f;
                    d[2] = s3f - s1f;
                    d[3] = s4f - s2f;
                    d[4] = -1.0f;
                    out[(size_t)BB * KK * 5 + (size_t)b * KK + slotk] = 0.0f;
                }
                __syncthreads();   // wsum reuse guard (uniform)
            }
        }
    }
}

// ======== K3: conflict pairs + last-tile-done greedy resolution ========
__global__ void __launch_bounds__(256) k3_pairs_resolve(float* __restrict__ out) {
    int b = blockIdx.y, bx = blockIdx.x;
    int t = threadIdx.x;

    int Nv = __ldg(&g_nv[b]);
    int nt = (Nv + TILE - 1) / TILE;
    int T = nt * (nt + 1) / 2;
    if (bx >= T) return;

    __shared__ float4 sbi[TILE];
    __shared__ float  sai[TILE];
    __shared__ float4 sbj[TILE];
    __shared__ float  saj[TILE];
    __shared__ int    swin;
    __shared__ unsigned sp[PCAP];        // 2 KB
    __shared__ unsigned char skeep[KK];  // 2 KB

    int i = 0, S = 0;
    while (bx >= S + (nt - i)) { S += nt - i; i++; }
    int j = i + (bx - S);
    int i0 = i * TILE, j0 = j * TILE;

    if (t < TILE) {
        float4 bi = (i0 + t < Nv) ? g_boxes[b][i0 + t] : make_float4(0.f, 0.f, 0.f, 0.f);
        sbi[t] = bi; sai[t] = (bi.z - bi.x) * (bi.w - bi.y);
    } else if (t < 2 * TILE) {
        int u = t - TILE;
        float4 bj = (j0 + u < Nv) ? g_boxes[b][j0 + u] : make_float4(0.f, 0.f, 0.f, 0.f);
        sbj[u] = bj; saj[u] = (bj.z - bj.x) * (bj.w - bj.y);
    }
    __syncthreads();

    int jl = t & 63;
    int jj = j0 + jl;
    if (jj < Nv) {
        float4 bj = sbj[jl];
        float aj = saj[jl];
        #pragma unroll
        for (int q = 0; q < 16; q++) {
            int ii = (t >> 6) + q * 4;
            int gi = i0 + ii;
            if (gi >= Nv || gi >= jj) continue;
            float4 bi = sbi[ii];
            float lx = fmaxf(bi.x, bj.x), ly = fmaxf(bi.y, bj.y);
            float rx = fminf(bi.z, bj.z), ry = fminf(bi.w, bj.w);
            float iw = fmaxf(rx - lx, 0.f), ih = fmaxf(ry - ly, 0.f);
            float inter = iw * ih;
            // iou > 0.7  <=>  inter > 0.7 * union   (union > 0)
            if (inter > 0.7f * (sai[ii] + aj - inter)) {
                unsigned pos = atomicAdd(&g_paircnt[b], 1u);
                if (pos < PCAP)
                    g_pairs[b][pos] = ((unsigned)jj << 16) | (unsigned)gi;
            }
        }
    }
    __syncthreads();

    if (t == 0) {
        __threadfence();                                  // publish this tile's pair writes
        unsigned old = atomicAdd(&g_tiledone[b], 1u);
        swin = (old == (unsigned)(T - 1)) ? 1 : 0;
    }
    __syncthreads();
    if (!swin) return;

    // ---- winner block: exact greedy resolution ----
    __threadfence();
    unsigned n = g_paircnt[b];
    if (n > PCAP) n = PCAP;

    for (int k = t; k < KK; k += 256) skeep[k] = (k < Nv) ? 1 : 0;
    for (unsigned p = t; p < n; p += 256) sp[p] = g_pairs[b][p];
    __syncthreads();

    if (t == 0) {
        for (unsigned x = 1; x < n; x++) {
            unsigned v = sp[x];
            int y = (int)x - 1;
            while (y >= 0 && sp[y] > v) { sp[y + 1] = sp[y]; y--; }
            sp[y + 1] = v;
        }
        for (unsigned x = 0; x < n; x++) {
            unsigned v = sp[x];
            int jd = (int)(v >> 16), is = (int)(v & 0xFFFFu);
            if (skeep[is] && skeep[jd]) {
                skeep[jd] = 0;
                out[(size_t)BB * KK * 5 + (size_t)b * KK + jd] = 0.0f;
            }
        }
        g_paircnt[b]  = 0u;   // restore zero-state for next launch
        g_tiledone[b] = 0u;
    }
}

// ---------------- launch ----------------
extern "C" void kernel_launch(void* const* d_in, const int* in_sizes, int n_in,
                              void* d_out, int out_size) {
    const float* preds = (const float*)d_in[0];
    float* out = (float*)d_out;
    (void)in_sizes; (void)n_in; (void)out_size;

    k1_compact      <<<dim3(27, BB), 256>>>(preds);       // 27*1024 >= 26880
    k2_rank_tail    <<<dim3(RB, BB), 256>>>(preds, out);
    k3_pairs_resolve<<<dim3(528, BB), 256>>>(out);        // 528 = max tiles (Nv<=2048)
}

// round 8
// speedup vs baseline: 2.5906x; 1.0106x over previous
#include <cuda_runtime.h>
#include <cuda_bf16.h>
#include <stdint.h>

#define BB 8
#define AA 26880
#define KK 2048
#define NCH 105          // 26880/256 chunks per batch
#define SCAP 4096        // staged-key capacity (Nv ~ 1344)
#define PCAP 512         // conflict-pair capacity per batch (expected ~10)
#define RB 32            // rank/tail blocks per batch in K2
#define TILE 64

// ---------------- device scratch ----------------
__device__ unsigned            g_cvcnt[BB * NCH];          // per-chunk valid count
__device__ unsigned long long  g_ckeys[BB * NCH * 256];    // chunk-local compacted keys
__device__ int                 g_nv[BB];
__device__ float4              g_boxes[BB][KK];
__device__ unsigned            g_paircnt[BB];              // 0 at entry, reset by K3 winner
__device__ unsigned            g_pairs[BB][PCAP];
__device__ unsigned            g_tiledone[BB];             // 0 at entry, reset by K3 winner

// ======== K1: vectorized chunked compaction (float4, warp-scan, no atomics) ========
// key = (score_bits << 32) | (0xFFFFFFFF - idx): descending key order gives
// score desc, idx asc on ties (positive floats are bit-order-preserving).
__global__ void __launch_bounds__(256) k1_compact(const float* __restrict__ preds) {
    int b = blockIdx.y;
    int t = threadIdx.x, wid = t >> 5, lane = t & 31;
    __shared__ unsigned swc[8];    // per-warp valid totals

    int a0 = blockIdx.x * 1024 + t * 4;          // 4 consecutive anchors per thread
    bool inb = (a0 < AA);                        // AA % 4 == 0, float4-aligned
    float4 s4 = make_float4(0.f, 0.f, 0.f, 0.f);
    if (inb) s4 = *(const float4*)(preds + (size_t)b * 5 * AA + (size_t)4 * AA + a0);

    unsigned m = 0;
    if (inb) {
        m = (unsigned)(s4.x >= 0.1f)
          | ((unsigned)(s4.y >= 0.1f) << 1)
          | ((unsigned)(s4.z >= 0.1f) << 2)
          | ((unsigned)(s4.w >= 0.1f) << 3);
    }
    int v = __popc(m);
    // warp inclusive scan of v
    int inc = v;
    #pragma unroll
    for (int off = 1; off < 32; off <<= 1) {
        int n = __shfl_up_sync(0xFFFFFFFFu, inc, off);
        if (lane >= off) inc += n;
    }
    int exc = inc - v;
    if (lane == 31) swc[wid] = (unsigned)inc;
    __syncthreads();

    int cib = wid >> 1;                    // chunk within block (0..3), chunk = 2 warps
    int cl = blockIdx.x * 4 + cib;
    if (cl < NCH && inb) {
        unsigned p = (unsigned)exc + ((wid & 1) ? swc[wid - 1] : 0u);
        unsigned long long* dst = &g_ckeys[((size_t)b * NCH + cl) * 256];
        float ss[4] = {s4.x, s4.y, s4.z, s4.w};
        #pragma unroll
        for (int q = 0; q < 4; q++) {
            if ((m >> q) & 1u) {
                dst[p++] =
                    ((unsigned long long)__float_as_uint(ss[q]) << 32) |
                    (unsigned long long)(0xFFFFFFFFu - (unsigned)(a0 + q));
            }
        }
    }
    if (cl < NCH && (t & 63) == 0)
        g_cvcnt[b * NCH + cl] = swc[cib * 2] + swc[cib * 2 + 1];

    // PDL: allow K2's grid to launch as early as possible
    cudaTriggerProgrammaticLaunchCompletion();
}

// ======== K2: rank sort (thread-per-candidate, 4-way split scan) + tail fill ========
__global__ void __launch_bounds__(256) k2_rank_tail(const float* __restrict__ preds,
                                                    float* __restrict__ out) {
    // PDL: wait until K1's writes (g_cvcnt, g_ckeys) are visible
    cudaGridDependencySynchronize();

    int b = blockIdx.y, bl = blockIdx.x;       // bl in [0, RB)
    int t = threadIdx.x, wid = t >> 5, lane = t & 31;

    __shared__ unsigned long long sk[SCAP];    // 32 KB
    __shared__ unsigned scv[NCH];
    __shared__ unsigned scpre[NCH + 1];
    __shared__ unsigned short rp[64][4];
    __shared__ unsigned wsum[8];
    __shared__ unsigned s_cnt;

    if (t < NCH) scv[t] = g_cvcnt[b * NCH + t];
    __syncthreads();
    if (t == 0) {
        unsigned run = 0;
        for (int x = 0; x < NCH; x++) { scpre[x] = run; run += scv[x]; }
        scpre[NCH] = run;
        s_cnt = (run > SCAP) ? SCAP : run;
    }
    __syncthreads();
    unsigned cnt = s_cnt;
    int Nv = ((int)cnt < KK) ? (int)cnt : KK;
    if (bl == 0 && t == 0) g_nv[b] = Nv;

    // stage keys contiguously (warp per chunk)
    for (int cl = wid; cl < NCH; cl += 8) {
        unsigned base = scpre[cl], n = scv[cl];
        const unsigned long long* src = &g_ckeys[((size_t)b * NCH + cl) * 256];
        for (unsigned j = lane; j < n; j += 32) {
            unsigned d = base + j;
            if (d < SCAP) sk[d] = __ldg(&src[j]);
        }
    }
    __syncthreads();

    // ---- rank scan: slot = candidate lane, seg = key segment ----
    int slot = t & 63, seg = t >> 6;           // seg is warp-uniform
    int npass = ((int)cnt + RB * 64 - 1) / (RB * 64);
    const float* basep = preds + (size_t)b * 5 * AA;

    for (int p = 0; p < npass; p++) {
        int c = p * (RB * 64) + bl * 64 + slot;
        bool act = (c < (int)cnt);
        unsigned long long mykey = act ? sk[c] : 0ULL;
        int s0 = (int)(((long long)cnt * seg) >> 2);
        int s1 = (int)(((long long)cnt * (seg + 1)) >> 2);
        int rpart = 0;
        if (act) {
            int mm = s0;
            for (; mm + 4 <= s1; mm += 4) {    // broadcast LDS: all lanes same address
                rpart += (sk[mm]     > mykey);
                rpart += (sk[mm + 1] > mykey);
                rpart += (sk[mm + 2] > mykey);
                rpart += (sk[mm + 3] > mykey);
            }
            for (; mm < s1; mm++) rpart += (sk[mm] > mykey);
        }
        rp[slot][seg] = (unsigned short)rpart;
        __syncthreads();
        if (seg == 0 && act) {
            int r = (int)rp[slot][0] + rp[slot][1] + rp[slot][2] + rp[slot][3];
            if (r < KK) {
                int idx = (int)(0xFFFFFFFFu - (unsigned)(mykey & 0xFFFFFFFFu));
                float score = __uint_as_float((unsigned)(mykey >> 32));
                float cx = __ldg(&basep[idx]);
                float cy = __ldg(&basep[AA + idx]);
                float ww = __ldg(&basep[2 * AA + idx]);
                float hh = __ldg(&basep[3 * AA + idx]);
                float hw = ww * 0.5f, hv = hh * 0.5f;
                float x1 = cx - hw, y1 = cy - hv, x2 = cx + hw, y2 = cy + hv;
                g_boxes[b][r] = make_float4(x1, y1, x2, y2);
                // scale = DET_SCALE/IMG_SIZE = [1.5, 1.0546875] (exact fp32)
                float s1f = x1 * 1.5f + 1.0f;
                float s2f = y1 * 1.0546875f + 1.0f;
                float s3f = x2 * 1.5f + 1.0f;
                float s4f = y2 * 1.0546875f + 1.0f;
                float* d = out + ((size_t)b * KK + r) * 5;
                d[0] = (s1f + s3f) * 0.5f;
                d[1] = (s2f + s4f) * 0.5f;
                d[2] = s3f - s1f;
                d[3] = s4f - s2f;
                d[4] = score;
                out[(size_t)BB * KK * 5 + (size_t)b * KK + r] = 1.0f;
            }
        }
        __syncthreads();
    }

    // ---- tail fill: this block handles chunks bl, bl+RB, ... ----
    int needed = KK - Nv;
    if (needed > 0) {
        const float* sc = basep + (size_t)4 * AA;
        for (int cl = bl; cl < NCH; cl += RB) {
            int invpre = 256 * cl - (int)scpre[cl];   // block-uniform
            if (invpre < needed) {                    // uniform branch
                int a = cl * 256 + t;
                float s = __ldg(&sc[a]);
                bool inv = (s < 0.1f);
                unsigned bal = __ballot_sync(0xFFFFFFFFu, inv);
                if (lane == 0) wsum[wid] = (unsigned)__popc(bal);
                __syncthreads();
                int wbase = 0;
                #pragma unroll
                for (int q = 0; q < 8; q++) if (q < wid) wbase += (int)wsum[q];
                int r = invpre + wbase + __popc(bal & ((1u << lane) - 1u));
                if (inv && r < needed) {
                    int slotk = Nv + r;
                    float cx = basep[a], cy = basep[AA + a];
                    float ww = basep[2 * AA + a], hh = basep[3 * AA + a];
                    float hw = ww * 0.5f, hv = hh * 0.5f;
                    float x1 = cx - hw, y1 = cy - hv, x2 = cx + hw, y2 = cy + hv;
                    float s1f = x1 * 1.5f + 1.0f;
                    float s2f = y1 * 1.0546875f + 1.0f;
                    float s3f = x2 * 1.5f + 1.0f;
                    float s4f = y2 * 1.0546875f + 1.0f;
                    float* d = out + ((size_t)b * KK + slotk) * 5;
                    d[0] = (s1f + s3f) * 0.5f;
                    d[1] = (s2f + s4f) * 0.5f;
                    d[2] = s3f - s1f;
                    d[3] = s4f - s2f;
                    d[4] = -1.0f;
                    out[(size_t)BB * KK * 5 + (size_t)b * KK + slotk] = 0.0f;
                }
                __syncthreads();   // wsum reuse guard (uniform)
            }
        }
    }

    // PDL: allow K3's grid to launch as early as possible
    cudaTriggerProgrammaticLaunchCompletion();
}

// ======== K3: conflict pairs + last-tile-done greedy resolution ========
__global__ void __launch_bounds__(256) k3_pairs_resolve(float* __restrict__ out) {
    // PDL: wait until K2's writes (g_nv, g_boxes, out) are visible
    cudaGridDependencySynchronize();

    int b = blockIdx.y, bx = blockIdx.x;
    int t = threadIdx.x;

    int Nv = __ldg(&g_nv[b]);
    int nt = (Nv + TILE - 1) / TILE;
    int T = nt * (nt + 1) / 2;
    if (bx >= T) return;

    __shared__ float4 sbi[TILE];
    __shared__ float  sai[TILE];
    __shared__ float4 sbj[TILE];
    __shared__ float  saj[TILE];
    __shared__ int    swin;
    __shared__ unsigned sp[PCAP];        // 2 KB
    __shared__ unsigned char skeep[KK];  // 2 KB

    int i = 0, S = 0;
    while (bx >= S + (nt - i)) { S += nt - i; i++; }
    int j = i + (bx - S);
    int i0 = i * TILE, j0 = j * TILE;

    if (t < TILE) {
        float4 bi = (i0 + t < Nv) ? g_boxes[b][i0 + t] : make_float4(0.f, 0.f, 0.f, 0.f);
        sbi[t] = bi; sai[t] = (bi.z - bi.x) * (bi.w - bi.y);
    } else if (t < 2 * TILE) {
        int u = t - TILE;
        float4 bj = (j0 + u < Nv) ? g_boxes[b][j0 + u] : make_float4(0.f, 0.f, 0.f, 0.f);
        sbj[u] = bj; saj[u] = (bj.z - bj.x) * (bj.w - bj.y);
    }
    __syncthreads();

    int jl = t & 63;
    int jj = j0 + jl;
    if (jj < Nv) {
        float4 bj = sbj[jl];
        float aj = saj[jl];
        #pragma unroll
        for (int q = 0; q < 16; q++) {
            int ii = (t >> 6) + q * 4;
            int gi = i0 + ii;
            if (gi >= Nv || gi >= jj) continue;
            float4 bi = sbi[ii];
            float lx = fmaxf(bi.x, bj.x), ly = fmaxf(bi.y, bj.y);
            float rx = fminf(bi.z, bj.z), ry = fminf(bi.w, bj.w);
            float iw = fmaxf(rx - lx, 0.f), ih = fmaxf(ry - ly, 0.f);
            float inter = iw * ih;
            // iou > 0.7  <=>  inter > 0.7 * union   (union > 0)
            if (inter > 0.7f * (sai[ii] + aj - inter)) {
                unsigned pos = atomicAdd(&g_paircnt[b], 1u);
                if (pos < PCAP)
                    g_pairs[b][pos] = ((unsigned)jj << 16) | (unsigned)gi;
            }
        }
    }
    __syncthreads();

    if (t == 0) {
        __threadfence();                                  // publish this tile's pair writes
        unsigned old = atomicAdd(&g_tiledone[b], 1u);
        swin = (old == (unsigned)(T - 1)) ? 1 : 0;
    }
    __syncthreads();
    if (!swin) return;

    // ---- winner block: exact greedy resolution ----
    __threadfence();
    unsigned n = g_paircnt[b];
    if (n > PCAP) n = PCAP;

    for (int k = t; k < KK; k += 256) skeep[k] = (k < Nv) ? 1 : 0;
    for (unsigned p = t; p < n; p += 256) sp[p] = g_pairs[b][p];
    __syncthreads();

    if (t == 0) {
        for (unsigned x = 1; x < n; x++) {
            unsigned v = sp[x];
            int y = (int)x - 1;
            while (y >= 0 && sp[y] > v) { sp[y + 1] = sp[y]; y--; }
            sp[y + 1] = v;
        }
        for (unsigned x = 0; x < n; x++) {
            unsigned v = sp[x];
            int jd = (int)(v >> 16), is = (int)(v & 0xFFFFu);
            if (skeep[is] && skeep[jd]) {
                skeep[jd] = 0;
                out[(size_t)BB * KK * 5 + (size_t)b * KK + jd] = 0.0f;
            }
        }
        g_paircnt[b]  = 0u;   // restore zero-state for next launch
        g_tiledone[b] = 0u;
    }
}

// ---------------- launch (PDL-chained) ----------------
static void launch_pdl(void (*kern)(const float*, float*),
                       dim3 grid, const float* preds, float* out) {
    cudaLaunchConfig_t cfg = {};
    cfg.gridDim = grid;
    cfg.blockDim = dim3(256, 1, 1);
    cfg.dynamicSmemBytes = 0;
    cfg.stream = 0;
    cudaLaunchAttribute attr[1];
    attr[0].id = cudaLaunchAttributeProgrammaticStreamSerialization;
    attr[0].val.programmaticStreamSerializationAllowed = 1;
    cfg.attrs = attr;
    cfg.numAttrs = 1;
    cudaLaunchKernelEx(&cfg, kern, preds, out);
}

static void launch_pdl_out(void (*kern)(float*), dim3 grid, float* out) {
    cudaLaunchConfig_t cfg = {};
    cfg.gridDim = grid;
    cfg.blockDim = dim3(256, 1, 1);
    cfg.dynamicSmemBytes = 0;
    cfg.stream = 0;
    cudaLaunchAttribute attr[1];
    attr[0].id = cudaLaunchAttributeProgrammaticStreamSerialization;
    attr[0].val.programmaticStreamSerializationAllowed = 1;
    cfg.attrs = attr;
    cfg.numAttrs = 1;
    cudaLaunchKernelEx(&cfg, kern, out);
}

extern "C" void kernel_launch(void* const* d_in, const int* in_sizes, int n_in,
                              void* d_out, int out_size) {
    const float* preds = (const float*)d_in[0];
    float* out = (float*)d_out;
    (void)in_sizes; (void)n_in; (void)out_size;

    k1_compact<<<dim3(27, BB), 256>>>(preds);             // 27*1024 >= 26880
    launch_pdl(k2_rank_tail, dim3(RB, BB), preds, out);   // PDL on K1
    launch_pdl_out(k3_pairs_resolve, dim3(528, BB), out); // PDL on K2
}